// round 15
// baseline (speedup 1.0000x reference)
#include <cuda_runtime.h>
#include <cuda_bf16.h>
#include <math.h>

#define BB 128
#define NN 256
#define EE 1024
#define DD 128
#define HH 8
#define DKK 16
#define DIN 130   // D + 2 degree features
#define KP  144   // K padded to 9 * 16
#define KPS 152   // x smem row stride (bf16)
#define WPAD 136  // W smem row stride (bf16)
#define KTP 264   // K^T smem row stride (bf16): 528B, conflict-free ldmatrix

// ---------------- scratch (device globals; no runtime allocation) ----------------
__device__ float g_deg_r[BB * NN];
__device__ float g_deg_c[BB * NN];
__device__ float g_q[BB * HH * NN * DKK];
__device__ float g_k[BB * HH * NN * DKK];
__device__ float g_v[BB * HH * NN * DKK];
__device__ float g_ef[BB * EE];
__device__ float g_wvec[DD];
__device__ float g_bmean;
__device__ float g_o[BB * NN * DD];
__device__ int   g_mask[BB * NN];
__device__ int   g_csc_ptr[BB * 9];
__device__ int   g_csc_rc[BB * EE];   // (row<<5) | (col & 31)
__device__ int   g_csc_eid[BB * EE];
__device__ __nv_bfloat16 g_wh[3 * KP * DD];
__device__ __nv_bfloat16 g_wl[3 * KP * DD];

// ---------------- helpers ----------------
__device__ __forceinline__ unsigned smem_u32(const void* p) {
    return (unsigned)__cvta_generic_to_shared(p);
}
__device__ __forceinline__ void ldsm4(unsigned& r0, unsigned& r1, unsigned& r2,
                                      unsigned& r3, unsigned addr) {
    asm volatile("ldmatrix.sync.aligned.m8n8.x4.shared.b16 {%0,%1,%2,%3}, [%4];"
                 : "=r"(r0), "=r"(r1), "=r"(r2), "=r"(r3) : "r"(addr));
}
__device__ __forceinline__ void ldsm4t(unsigned& r0, unsigned& r1, unsigned& r2,
                                       unsigned& r3, unsigned addr) {
    asm volatile("ldmatrix.sync.aligned.m8n8.x4.trans.shared.b16 {%0,%1,%2,%3}, [%4];"
                 : "=r"(r0), "=r"(r1), "=r"(r2), "=r"(r3) : "r"(addr));
}
__device__ __forceinline__ void mma_bf16(float* c, unsigned a0, unsigned a1,
                                         unsigned a2, unsigned a3,
                                         unsigned b0, unsigned b1) {
    asm volatile("mma.sync.aligned.m16n8k16.row.col.f32.bf16.bf16.f32 "
                 "{%0,%1,%2,%3}, {%4,%5,%6,%7}, {%8,%9}, {%0,%1,%2,%3};"
                 : "+f"(c[0]), "+f"(c[1]), "+f"(c[2]), "+f"(c[3])
                 : "r"(a0), "r"(a1), "r"(a2), "r"(a3), "r"(b0), "r"(b1));
}
__device__ __forceinline__ void bsplit(float v, __nv_bfloat16& h, __nv_bfloat16& l) {
    h = __float2bfloat16(v);
    l = __float2bfloat16(v - __bfloat162float(h));
}
__device__ __forceinline__ unsigned pack_bf2(float x, float y) {
    __nv_bfloat162 v = __floats2bfloat162_rn(x, y);
    return *reinterpret_cast<unsigned*>(&v);
}
__device__ __forceinline__ unsigned pack_bf2_lo(float x, float y) {
    __nv_bfloat16 hx = __float2bfloat16(x), hy = __float2bfloat16(y);
    float lx = x - __bfloat162float(hx), ly = y - __bfloat162float(hy);
    __nv_bfloat162 v = __floats2bfloat162_rn(lx, ly);
    return *reinterpret_cast<unsigned*>(&v);
}

// ---------------- kernel 1: mask normalize + wvec (blocks<128) | W split (>=128) ----
__global__ void k_mask_conv(const void* __restrict__ mp,
                            const float* __restrict__ Wew,
                            const float* __restrict__ Web,
                            const float* __restrict__ Wq,
                            const float* __restrict__ Wk,
                            const float* __restrict__ Wv) {
    if (blockIdx.x >= 128) {
        int j = (blockIdx.x - 128) * 256 + threadIdx.x;  // < 3*KP*DD
        int m = j / (KP * DD);
        int rem = j - m * (KP * DD);
        int k = rem / DD, n = rem - k * DD;
        const float* W = (m == 0) ? Wq : (m == 1) ? Wk : Wv;
        float v = (k < DIN) ? W[k * DD + n] : 0.f;
        __nv_bfloat16 h, l;
        bsplit(v, h, l);
        g_wh[j] = h;
        g_wl[j] = l;
        return;
    }
    const unsigned int* mw = reinterpret_cast<const unsigned int*>(mp);
    __shared__ int c_f32, c_big;
    if (threadIdx.x == 0) { c_f32 = 0; c_big = 0; }
    __syncthreads();
    int nf = 0, nb = 0;
    for (int i = threadIdx.x; i < 8192; i += 256) {
        unsigned int w = mw[i];
        if (w == 0x3F800000u) nf++;
        else if (w > 1u) nb++;
    }
    if (nf) atomicAdd(&c_f32, nf);
    if (nb) atomicAdd(&c_big, nb);
    __syncthreads();
    int f = (c_f32 > 64) ? 2 : (c_big > 64) ? 0 : 1;
    int i = blockIdx.x * 256 + threadIdx.x;
    int v;
    if (f == 2)      v = (reinterpret_cast<const float*>(mp)[i] != 0.0f);
    else if (f == 1) v = (reinterpret_cast<const int*>(mp)[i] != 0);
    else             v = (reinterpret_cast<const unsigned char*>(mp)[i] != 0);
    g_mask[i] = v;

    if (blockIdx.x == 0 && threadIdx.x < DD) {
        int r = threadIdx.x;
        float s = 0.f;
        for (int j = 0; j < DD; j++) s += Wew[r * DD + j];
        g_wvec[r] = s * (1.0f / DD);
        if (r == 0) {
            float b = 0.f;
            for (int j = 0; j < DD; j++) b += Web[j];
            g_bmean = b * (1.0f / DD);
        }
    }
}

// ---------------- kernel 2: degrees + CSC-by-key-chunk + edge features -------------
__global__ void k_deg_csr(const int* __restrict__ ei, const float* __restrict__ ea) {
    int b = blockIdx.x, t = threadIdx.x;  // 256 threads
    __shared__ int hr[NN], hc[NN], bc[8], boff[8];
    hr[t] = 0; hc[t] = 0;
    if (t < 8) bc[t] = 0;
    __syncthreads();
    const int* rows = ei + b * 2 * EE;
    const int* cols = rows + EE;
    for (int e = t; e < EE; e += 256) {
        atomicAdd(&hr[rows[e]], 1);
        atomicAdd(&hc[cols[e]], 1);
        atomicAdd(&bc[cols[e] >> 5], 1);
    }
    __syncthreads();
    g_deg_r[b * NN + t] = (float)hr[t];
    g_deg_c[b * NN + t] = (float)hc[t];
    if (t == 0) {
        int s = 0;
        #pragma unroll
        for (int i = 0; i < 8; i++) {
            g_csc_ptr[b * 9 + i] = s;
            boff[i] = s;
            s += bc[i];
        }
        g_csc_ptr[b * 9 + 8] = s;
    }
    __syncthreads();
    for (int e = t; e < EE; e += 256) {
        int c = cols[e];
        int pos = atomicAdd(&boff[c >> 5], 1);
        g_csc_rc[b * EE + pos] = (rows[e] << 5) | (c & 31);
        g_csc_eid[b * EE + pos] = e;
    }
    // edge features: warp per edge, dot(ea[e], wvec) + bmean
    int warp = t >> 5, lane = t & 31;
    float4 w4 = *reinterpret_cast<const float4*>(g_wvec + lane * 4);
    float bm = g_bmean;
    for (int e = warp; e < EE; e += 8) {
        const float* row = ea + ((size_t)b * EE + e) * DD;
        float4 a = *reinterpret_cast<const float4*>(row + lane * 4);
        float d = a.x * w4.x + a.y * w4.y + a.z * w4.z + a.w * w4.w;
        #pragma unroll
        for (int o = 16; o; o >>= 1) d += __shfl_xor_sync(0xFFFFFFFFu, d, o);
        if (lane == 0) g_ef[b * EE + e] = d + bm;
    }
}

// ---------------- kernel 3: QKV via tensor cores (unchanged from R14) --------------
__global__ void __launch_bounds__(256) k_qkv_mma(const float* __restrict__ x) {
    extern __shared__ __nv_bfloat16 ws[];
    __nv_bfloat16* xh_s = ws;
    __nv_bfloat16* xl_s = ws + 128 * KPS;
    __nv_bfloat16* wh_s = ws + 2 * 128 * KPS;
    __nv_bfloat16* wl_s = wh_s + 16 * WPAD;
    int t = threadIdx.x, warp = t >> 5, lane = t & 31;
    int r0blk = blockIdx.x * 128;
    int r0 = r0blk + warp * 16;

    const float* xb = x + (size_t)r0blk * DD;
    for (int i = t; i < 128 * 32; i += 256) {
        int row = i >> 5, c4 = (i & 31) << 2;
        float4 v = *reinterpret_cast<const float4*>(xb + row * DD + c4);
        __nv_bfloat16 h, l;
        int o = row * KPS + c4;
        bsplit(v.x, h, l); xh_s[o]     = h; xl_s[o]     = l;
        bsplit(v.y, h, l); xh_s[o + 1] = h; xl_s[o + 1] = l;
        bsplit(v.z, h, l); xh_s[o + 2] = h; xl_s[o + 2] = l;
        bsplit(v.w, h, l); xh_s[o + 3] = h; xl_s[o + 3] = l;
    }
    for (int i = t; i < 128 * (KPS - DD); i += 256) {
        int row = i / (KPS - DD), c = DD + i - row * (KPS - DD);
        float v = (c == 128) ? g_deg_r[r0blk + row]
                : (c == 129) ? g_deg_c[r0blk + row] : 0.f;
        __nv_bfloat16 h, l;
        bsplit(v, h, l);
        xh_s[row * KPS + c] = h;
        xl_s[row * KPS + c] = l;
    }

    unsigned xa_off = ((warp * 16 + (lane & 15)) * KPS) * 2 + ((lane >> 4) * 16);
    unsigned xh_base = smem_u32(xh_s) + xa_off;
    unsigned xl_base = smem_u32(xl_s) + xa_off;
    unsigned wb_off = (lane & 15) * (WPAD * 2) + ((lane >> 4) * 16);
    unsigned wh_base = smem_u32(wh_s) + wb_off;
    unsigned wl_base = smem_u32(wl_s) + wb_off;

    int g = lane >> 2;
    int cpair = (lane & 3) * 2;

    for (int m = 0; m < 3; m++) {
        float acc[16][4];
        #pragma unroll
        for (int i = 0; i < 16; i++)
            #pragma unroll
            for (int j = 0; j < 4; j++) acc[i][j] = 0.f;

        for (int kb = 0; kb < KP / 16; kb++) {
            __syncthreads();
            {
                const unsigned* srcH = reinterpret_cast<const unsigned*>(
                    g_wh + (m * KP + kb * 16) * DD);
                const unsigned* srcL = reinterpret_cast<const unsigned*>(
                    g_wl + (m * KP + kb * 16) * DD);
                unsigned* dstH = reinterpret_cast<unsigned*>(wh_s);
                unsigned* dstL = reinterpret_cast<unsigned*>(wl_s);
                #pragma unroll
                for (int i = t; i < 16 * 64; i += 256) {
                    int k = i >> 6, c = i & 63;
                    dstH[k * (WPAD / 2) + c] = srcH[i];
                    dstL[k * (WPAD / 2) + c] = srcL[i];
                }
            }
            __syncthreads();

            unsigned ah0, ah1, ah2, ah3, al0, al1, al2, al3;
            ldsm4(ah0, ah1, ah2, ah3, xh_base + kb * 32);
            ldsm4(al0, al1, al2, al3, xl_base + kb * 32);

            #pragma unroll
            for (int ntp = 0; ntp < 8; ntp++) {
                unsigned bh0, bh1, bh2, bh3, bl0, bl1, bl2, bl3;
                ldsm4t(bh0, bh1, bh2, bh3, wh_base + ntp * 32);
                ldsm4t(bl0, bl1, bl2, bl3, wl_base + ntp * 32);
                mma_bf16(acc[2 * ntp],     ah0, ah1, ah2, ah3, bh0, bh1);
                mma_bf16(acc[2 * ntp],     al0, al1, al2, al3, bh0, bh1);
                mma_bf16(acc[2 * ntp],     ah0, ah1, ah2, ah3, bl0, bl1);
                mma_bf16(acc[2 * ntp + 1], ah0, ah1, ah2, ah3, bh2, bh3);
                mma_bf16(acc[2 * ntp + 1], al0, al1, al2, al3, bh2, bh3);
                mma_bf16(acc[2 * ntp + 1], ah0, ah1, ah2, ah3, bl2, bl3);
            }
        }

        float* out = (m == 0) ? g_q : (m == 1) ? g_k : g_v;
        int tok0 = r0 + g, tok1 = tok0 + 8;
        int b0i = tok0 >> 8, n0i = tok0 & 255;
        int b1i = tok1 >> 8, n1i = tok1 & 255;
        #pragma unroll
        for (int nt = 0; nt < 16; nt++) {
            int c = nt * 8 + cpair;
            int h = c >> 4, dk = c & 15;
            *reinterpret_cast<float2*>(out + ((size_t)(b0i * HH + h) * NN + n0i) * DKK + dk)
                = make_float2(acc[nt][0], acc[nt][1]);
            *reinterpret_cast<float2*>(out + ((size_t)(b1i * HH + h) * NN + n1i) * DKK + dk)
                = make_float2(acc[nt][2], acc[nt][3]);
        }
    }
}

// ---------------- kernel 4: tensor-core attention --------------------------------
// Block per (b,h), 256 threads (8 warps x 32 queries). 32-key chunks.
// S goes through smem for exact edge-bias scatter; P repacked in registers for PV.
__global__ void __launch_bounds__(256) k_attn2() {
    extern __shared__ char asm_[];
    float*         Ssm  = reinterpret_cast<float*>(asm_);                 // [256][34]
    __nv_bfloat16* khT  = reinterpret_cast<__nv_bfloat16*>(asm_ + 34816); // [16][KTP]
    __nv_bfloat16* klT  = khT + 16 * KTP;
    __nv_bfloat16* vh_s = klT + 16 * KTP;                                  // [256][16]
    __nv_bfloat16* vl_s = vh_s + NN * 16;
    __nv_bfloat16* qh_s = vl_s + NN * 16;                                  // [256][16]
    __nv_bfloat16* ql_s = qh_s + NN * 16;
    float*         maskb = reinterpret_cast<float*>(ql_s + NN * 16);       // [256]
    int*           cscp  = reinterpret_cast<int*>(maskb + NN);             // [9]

    int bh = blockIdx.x, b = bh >> 3, h = bh & 7;
    int t = threadIdx.x, warp = t >> 5, lane = t & 31;
    int g = lane >> 2, cp = (lane & 3) * 2;

    // ---- stage: thread t <-> token t ----
    {
        const float4* qg = reinterpret_cast<const float4*>(g_q + ((size_t)bh * NN + t) * DKK);
        const float4* kg = reinterpret_cast<const float4*>(g_k + ((size_t)bh * NN + t) * DKK);
        const float4* vg = reinterpret_cast<const float4*>(g_v + ((size_t)bh * NN + t) * DKK);
        float qv[16], kv[16], vv[16];
        #pragma unroll
        for (int i = 0; i < 4; i++) {
            float4 a = qg[i];
            qv[4*i] = a.x; qv[4*i+1] = a.y; qv[4*i+2] = a.z; qv[4*i+3] = a.w;
            a = kg[i];
            kv[4*i] = a.x; kv[4*i+1] = a.y; kv[4*i+2] = a.z; kv[4*i+3] = a.w;
            a = vg[i];
            vv[4*i] = a.x; vv[4*i+1] = a.y; vv[4*i+2] = a.z; vv[4*i+3] = a.w;
        }
        unsigned* qh = reinterpret_cast<unsigned*>(qh_s) + t * 8;
        unsigned* ql = reinterpret_cast<unsigned*>(ql_s) + t * 8;
        unsigned* vh = reinterpret_cast<unsigned*>(vh_s) + t * 8;
        unsigned* vl = reinterpret_cast<unsigned*>(vl_s) + t * 8;
        #pragma unroll
        for (int i = 0; i < 8; i++) {
            qh[i] = pack_bf2(qv[2*i], qv[2*i+1]);
            ql[i] = pack_bf2_lo(qv[2*i], qv[2*i+1]);
            vh[i] = pack_bf2(vv[2*i], vv[2*i+1]);
            vl[i] = pack_bf2_lo(vv[2*i], vv[2*i+1]);
        }
        #pragma unroll
        for (int dk = 0; dk < 16; dk++) {
            __nv_bfloat16 hh, ll;
            bsplit(kv[dk], hh, ll);
            khT[dk * KTP + t] = hh;
            klT[dk * KTP + t] = ll;
        }
        maskb[t] = g_mask[b * NN + t] ? 0.f : -10000.f;
        if (t < 9) cscp[t] = g_csc_ptr[b * 9 + t];
    }
    __syncthreads();

    // ---- Q A-fragments (persist) ----
    unsigned qfh[2][4], qfl[2][4];
    #pragma unroll
    for (int mi = 0; mi < 2; mi++) {
        unsigned off = ((warp * 32 + mi * 16 + (lane & 15)) * 16) * 2 + (lane >> 4) * 16;
        ldsm4(qfh[mi][0], qfh[mi][1], qfh[mi][2], qfh[mi][3], smem_u32(qh_s) + off);
        ldsm4(qfl[mi][0], qfl[mi][1], qfl[mi][2], qfl[mi][3], smem_u32(ql_s) + off);
    }

    float lsum[2][2] = {{0.f, 0.f}, {0.f, 0.f}};
    float oacc[2][2][4];
    #pragma unroll
    for (int mi = 0; mi < 2; mi++)
        #pragma unroll
        for (int nv = 0; nv < 2; nv++)
            #pragma unroll
            for (int j = 0; j < 4; j++) oacc[mi][nv][j] = 0.f;

    for (int ch = 0; ch < 8; ch++) {
        int c0 = ch * 32;
        // K B-fragments: [k=dk16][n=keys], 2 ldsm4t per split
        unsigned kbh[4][2], kbl[4][2];
        #pragma unroll
        for (int hf = 0; hf < 2; hf++) {
            unsigned off = ((lane & 15) * KTP + c0 + hf * 16) * 2 + (lane >> 4) * 16;
            unsigned r0, r1, r2, r3;
            ldsm4t(r0, r1, r2, r3, smem_u32(khT) + off);
            kbh[2*hf][0] = r0; kbh[2*hf][1] = r1; kbh[2*hf+1][0] = r2; kbh[2*hf+1][1] = r3;
            ldsm4t(r0, r1, r2, r3, smem_u32(klT) + off);
            kbl[2*hf][0] = r0; kbl[2*hf][1] = r1; kbl[2*hf+1][0] = r2; kbl[2*hf+1][1] = r3;
        }
        // QK^T (split x3) and store S to smem with scale + mask bias
        #pragma unroll
        for (int mi = 0; mi < 2; mi++) {
            int r0 = warp * 32 + mi * 16 + g;
            #pragma unroll
            for (int nt = 0; nt < 4; nt++) {
                float S[4] = {0.f, 0.f, 0.f, 0.f};
                mma_bf16(S, qfh[mi][0], qfh[mi][1], qfh[mi][2], qfh[mi][3], kbh[nt][0], kbh[nt][1]);
                mma_bf16(S, qfl[mi][0], qfl[mi][1], qfl[mi][2], qfl[mi][3], kbh[nt][0], kbh[nt][1]);
                mma_bf16(S, qfh[mi][0], qfh[mi][1], qfh[mi][2], qfh[mi][3], kbl[nt][0], kbl[nt][1]);
                int cl = nt * 8 + cp;
                float2 mb = *reinterpret_cast<float2*>(&maskb[c0 + cl]);
                *reinterpret_cast<float2*>(&Ssm[r0 * 34 + cl]) =
                    make_float2(S[0] * 0.25f + mb.x, S[1] * 0.25f + mb.y);
                *reinterpret_cast<float2*>(&Ssm[(r0 + 8) * 34 + cl]) =
                    make_float2(S[2] * 0.25f + mb.x, S[3] * 0.25f + mb.y);
            }
        }
        __syncthreads();
        // scatter edge bias (exact reference math: bias added pre-softmax)
        for (int i = cscp[ch] + t; i < cscp[ch + 1]; i += 256) {
            int rc = g_csc_rc[b * EE + i];
            Ssm[(rc >> 5) * 34 + (rc & 31)] += g_ef[b * EE + g_csc_eid[b * EE + i]];
        }
        __syncthreads();
        // exp + rowsum + PV per m-tile
        #pragma unroll
        for (int mi = 0; mi < 2; mi++) {
            int r0 = warp * 32 + mi * 16 + g;
            float pe[4][4];
            float rs0 = 0.f, rs1 = 0.f;
            #pragma unroll
            for (int nt = 0; nt < 4; nt++) {
                int cl = nt * 8 + cp;
                float2 s01 = *reinterpret_cast<float2*>(&Ssm[r0 * 34 + cl]);
                float2 s23 = *reinterpret_cast<float2*>(&Ssm[(r0 + 8) * 34 + cl]);
                pe[nt][0] = __expf(s01.x);
                pe[nt][1] = __expf(s01.y);
                pe[nt][2] = __expf(s23.x);
                pe[nt][3] = __expf(s23.y);
                rs0 += pe[nt][0] + pe[nt][1];
                rs1 += pe[nt][2] + pe[nt][3];
            }
            rs0 += __shfl_xor_sync(0xFFFFFFFFu, rs0, 1);
            rs0 += __shfl_xor_sync(0xFFFFFFFFu, rs0, 2);
            rs1 += __shfl_xor_sync(0xFFFFFFFFu, rs1, 1);
            rs1 += __shfl_xor_sync(0xFFFFFFFFu, rs1, 2);
            lsum[mi][0] += rs0;
            lsum[mi][1] += rs1;
            #pragma unroll
            for (int kt = 0; kt < 2; kt++) {
                // P c-frag -> A-frag repack (register-only)
                unsigned pah0 = pack_bf2(pe[2*kt][0],   pe[2*kt][1]);
                unsigned pah1 = pack_bf2(pe[2*kt][2],   pe[2*kt][3]);
                unsigned pah2 = pack_bf2(pe[2*kt+1][0], pe[2*kt+1][1]);
                unsigned pah3 = pack_bf2(pe[2*kt+1][2], pe[2*kt+1][3]);
                unsigned pal0 = pack_bf2_lo(pe[2*kt][0],   pe[2*kt][1]);
                unsigned pal1 = pack_bf2_lo(pe[2*kt][2],   pe[2*kt][3]);
                unsigned pal2 = pack_bf2_lo(pe[2*kt+1][0], pe[2*kt+1][1]);
                unsigned pal3 = pack_bf2_lo(pe[2*kt+1][2], pe[2*kt+1][3]);
                unsigned voff = ((c0 + kt * 16 + (lane & 15)) * 16) * 2 + (lane >> 4) * 16;
                unsigned vh0, vh1, vh2, vh3, vl0, vl1, vl2, vl3;
                ldsm4t(vh0, vh1, vh2, vh3, smem_u32(vh_s) + voff);
                ldsm4t(vl0, vl1, vl2, vl3, smem_u32(vl_s) + voff);
                mma_bf16(oacc[mi][0], pah0, pah1, pah2, pah3, vh0, vh1);
                mma_bf16(oacc[mi][0], pal0, pal1, pal2, pal3, vh0, vh1);
                mma_bf16(oacc[mi][0], pah0, pah1, pah2, pah3, vl0, vl1);
                mma_bf16(oacc[mi][1], pah0, pah1, pah2, pah3, vh2, vh3);
                mma_bf16(oacc[mi][1], pal0, pal1, pal2, pal3, vh2, vh3);
                mma_bf16(oacc[mi][1], pah0, pah1, pah2, pah3, vl2, vl3);
            }
        }
    }

    // ---- epilogue ----
    #pragma unroll
    for (int mi = 0; mi < 2; mi++) {
        float inv0 = 1.0f / lsum[mi][0];
        float inv1 = 1.0f / lsum[mi][1];
        int r0 = warp * 32 + mi * 16 + g;
        #pragma unroll
        for (int nv = 0; nv < 2; nv++) {
            int dk = nv * 8 + cp;
            *reinterpret_cast<float2*>(g_o + ((size_t)(b * NN + r0)) * DD + h * 16 + dk)
                = make_float2(oacc[mi][nv][0] * inv0, oacc[mi][nv][1] * inv0);
            *reinterpret_cast<float2*>(g_o + ((size_t)(b * NN + r0 + 8)) * DD + h * 16 + dk)
                = make_float2(oacc[mi][nv][2] * inv1, oacc[mi][nv][3] * inv1);
        }
    }
}

// ---------------- kernel 5: residual + layernorm ----------------
__global__ void k_ln(const float* __restrict__ x,
                     const float* __restrict__ lg,
                     const float* __restrict__ lb,
                     float* __restrict__ out) {
    int warp = threadIdx.x >> 5, lane = threadIdx.x & 31;
    int row = blockIdx.x * 8 + warp;
    int c0 = lane * 4;
    float4 o = *reinterpret_cast<const float4*>(g_o + (size_t)row * DD + c0);
    float4 xv = *reinterpret_cast<const float4*>(x + (size_t)row * DD + c0);
    float4 s = make_float4(o.x + xv.x, o.y + xv.y, o.z + xv.z, o.w + xv.w);
    float sum = s.x + s.y + s.z + s.w;
    float sq  = s.x * s.x + s.y * s.y + s.z * s.z + s.w * s.w;
    #pragma unroll
    for (int off = 16; off; off >>= 1) {
        sum += __shfl_xor_sync(0xFFFFFFFFu, sum, off);
        sq  += __shfl_xor_sync(0xFFFFFFFFu, sq, off);
    }
    float mu = sum * (1.0f / DD);
    float var = sq * (1.0f / DD) - mu * mu;
    float rstd = rsqrtf(var + 1e-6f);
    float4 g = *reinterpret_cast<const float4*>(lg + c0);
    float4 be = *reinterpret_cast<const float4*>(lb + c0);
    float4 r;
    r.x = (s.x - mu) * rstd * g.x + be.x;
    r.y = (s.y - mu) * rstd * g.y + be.y;
    r.z = (s.z - mu) * rstd * g.z + be.z;
    r.w = (s.w - mu) * rstd * g.w + be.w;
    *reinterpret_cast<float4*>(out + (size_t)row * DD + c0) = r;
}

// ---------------- launch ----------------
extern "C" void kernel_launch(void* const* d_in, const int* in_sizes, int n_in,
                              void* d_out, int out_size) {
    const float* x    = (const float*)d_in[0];
    const void*  mask = d_in[1];
    const int*   ei   = (const int*)d_in[2];
    const float* ea   = (const float*)d_in[3];
    const float* Wq   = (const float*)d_in[4];
    const float* Wk   = (const float*)d_in[5];
    const float* Wv   = (const float*)d_in[6];
    const float* Wew  = (const float*)d_in[7];
    const float* Web  = (const float*)d_in[8];
    const float* lg   = (const float*)d_in[9];
    const float* lb   = (const float*)d_in[10];
    float* out = (float*)d_out;

    k_mask_conv<<<128 + (3 * KP * DD) / 256, 256>>>(mask, Wew, Web, Wq, Wk, Wv);
    k_deg_csr<<<BB, 256>>>(ei, ea);

    int smem_mma = (2 * 128 * KPS + 2 * 16 * WPAD) * (int)sizeof(__nv_bfloat16);
    cudaFuncSetAttribute(k_qkv_mma, cudaFuncAttributeMaxDynamicSharedMemorySize, smem_mma);
    k_qkv_mma<<<(BB * NN) / 128, 256, smem_mma>>>(x);

    // launch #4 — profiled slot: the new tensor-core attention
    int smem_attn = 34816                                   // Ssm
                  + 2 * 16 * KTP * (int)sizeof(__nv_bfloat16)   // khT/klT
                  + 4 * NN * 16 * (int)sizeof(__nv_bfloat16)    // vh/vl/qh/ql
                  + NN * (int)sizeof(float)                     // maskb
                  + 9 * (int)sizeof(int) + 16;
    cudaFuncSetAttribute(k_attn2, cudaFuncAttributeMaxDynamicSharedMemorySize, smem_attn);
    k_attn2<<<BB * HH, 256, smem_attn>>>();

    k_ln<<<(BB * NN) / 8, 256>>>(x, lg, lb, out);
}

// round 16
// speedup vs baseline: 1.1715x; 1.1715x over previous
#include <cuda_runtime.h>
#include <cuda_bf16.h>
#include <math.h>

#define BB 128
#define NN 256
#define EE 1024
#define DD 128
#define HH 8
#define DKK 16
#define DIN 130   // D + 2 degree features
#define KP  144   // K padded to 9 * 16
#define KPS 152   // x smem row stride (bf16)
#define WPAD 136  // W smem row stride (bf16)
#define KTP 264   // K^T smem row stride (bf16)

// ---------------- scratch (device globals; no runtime allocation) ----------------
__device__ float g_deg_r[BB * NN];
__device__ float g_deg_c[BB * NN];
__device__ float g_q[BB * HH * NN * DKK];
__device__ float g_k[BB * HH * NN * DKK];
__device__ float g_v[BB * HH * NN * DKK];
__device__ float g_ef[BB * EE];
__device__ float g_wvec[DD];
__device__ float g_bmean;
__device__ float g_o[BB * NN * DD];
__device__ int   g_mask[BB * NN];
__device__ int   g_csr_ptr[BB * (NN + 1)];
__device__ int   g_csr_eid[BB * EE];
__device__ int   g_csr_col[BB * EE];
__device__ __nv_bfloat16 g_wh[3 * KP * DD];
__device__ __nv_bfloat16 g_wl[3 * KP * DD];

// ---------------- helpers ----------------
__device__ __forceinline__ unsigned smem_u32(const void* p) {
    return (unsigned)__cvta_generic_to_shared(p);
}
__device__ __forceinline__ void ldsm4(unsigned& r0, unsigned& r1, unsigned& r2,
                                      unsigned& r3, unsigned addr) {
    asm volatile("ldmatrix.sync.aligned.m8n8.x4.shared.b16 {%0,%1,%2,%3}, [%4];"
                 : "=r"(r0), "=r"(r1), "=r"(r2), "=r"(r3) : "r"(addr));
}
__device__ __forceinline__ void ldsm4t(unsigned& r0, unsigned& r1, unsigned& r2,
                                       unsigned& r3, unsigned addr) {
    asm volatile("ldmatrix.sync.aligned.m8n8.x4.trans.shared.b16 {%0,%1,%2,%3}, [%4];"
                 : "=r"(r0), "=r"(r1), "=r"(r2), "=r"(r3) : "r"(addr));
}
__device__ __forceinline__ void mma_bf16(float* c, unsigned a0, unsigned a1,
                                         unsigned a2, unsigned a3,
                                         unsigned b0, unsigned b1) {
    asm volatile("mma.sync.aligned.m16n8k16.row.col.f32.bf16.bf16.f32 "
                 "{%0,%1,%2,%3}, {%4,%5,%6,%7}, {%8,%9}, {%0,%1,%2,%3};"
                 : "+f"(c[0]), "+f"(c[1]), "+f"(c[2]), "+f"(c[3])
                 : "r"(a0), "r"(a1), "r"(a2), "r"(a3), "r"(b0), "r"(b1));
}
__device__ __forceinline__ void bsplit(float v, __nv_bfloat16& h, __nv_bfloat16& l) {
    h = __float2bfloat16(v);
    l = __float2bfloat16(v - __bfloat162float(h));
}
__device__ __forceinline__ unsigned pack_bf2(float x, float y) {
    __nv_bfloat162 v = __floats2bfloat162_rn(x, y);
    return *reinterpret_cast<unsigned*>(&v);
}
__device__ __forceinline__ unsigned pack_bf2_lo(float x, float y) {
    __nv_bfloat16 hx = __float2bfloat16(x), hy = __float2bfloat16(y);
    float lx = x - __bfloat162float(hx), ly = y - __bfloat162float(hy);
    __nv_bfloat162 v = __floats2bfloat162_rn(lx, ly);
    return *reinterpret_cast<unsigned*>(&v);
}

// ---------------- kernel 1: mask normalize + wvec (blocks<128) | W split (>=128) ----
__global__ void k_mask_conv(const void* __restrict__ mp,
                            const float* __restrict__ Wew,
                            const float* __restrict__ Web,
                            const float* __restrict__ Wq,
                            const float* __restrict__ Wk,
                            const float* __restrict__ Wv) {
    if (blockIdx.x >= 128) {
        int j = (blockIdx.x - 128) * 256 + threadIdx.x;
        int m = j / (KP * DD);
        int rem = j - m * (KP * DD);
        int k = rem / DD, n = rem - k * DD;
        const float* W = (m == 0) ? Wq : (m == 1) ? Wk : Wv;
        float v = (k < DIN) ? W[k * DD + n] : 0.f;
        __nv_bfloat16 h, l;
        bsplit(v, h, l);
        g_wh[j] = h;
        g_wl[j] = l;
        return;
    }
    const unsigned int* mw = reinterpret_cast<const unsigned int*>(mp);
    __shared__ int c_f32, c_big;
    if (threadIdx.x == 0) { c_f32 = 0; c_big = 0; }
    __syncthreads();
    int nf = 0, nb = 0;
    for (int i = threadIdx.x; i < 8192; i += 256) {
        unsigned int w = mw[i];
        if (w == 0x3F800000u) nf++;
        else if (w > 1u) nb++;
    }
    if (nf) atomicAdd(&c_f32, nf);
    if (nb) atomicAdd(&c_big, nb);
    __syncthreads();
    int f = (c_f32 > 64) ? 2 : (c_big > 64) ? 0 : 1;
    int i = blockIdx.x * 256 + threadIdx.x;
    int v;
    if (f == 2)      v = (reinterpret_cast<const float*>(mp)[i] != 0.0f);
    else if (f == 1) v = (reinterpret_cast<const int*>(mp)[i] != 0);
    else             v = (reinterpret_cast<const unsigned char*>(mp)[i] != 0);
    g_mask[i] = v;

    if (blockIdx.x == 0 && threadIdx.x < DD) {
        int r = threadIdx.x;
        float s = 0.f;
        for (int j = 0; j < DD; j++) s += Wew[r * DD + j];
        g_wvec[r] = s * (1.0f / DD);
        if (r == 0) {
            float b = 0.f;
            for (int j = 0; j < DD; j++) b += Web[j];
            g_bmean = b * (1.0f / DD);
        }
    }
}

// ---------------- kernel 2: degrees + row-CSR + edge features ----------------------
__global__ void k_deg_csr(const int* __restrict__ ei, const float* __restrict__ ea) {
    int b = blockIdx.x, t = threadIdx.x;  // 256 threads
    __shared__ int hr[NN], hc[NN], sc[NN], off[NN];
    hr[t] = 0; hc[t] = 0;
    __syncthreads();
    const int* rows = ei + b * 2 * EE;
    const int* cols = rows + EE;
    for (int e = t; e < EE; e += 256) {
        atomicAdd(&hr[rows[e]], 1);
        atomicAdd(&hc[cols[e]], 1);
    }
    __syncthreads();
    g_deg_r[b * NN + t] = (float)hr[t];
    g_deg_c[b * NN + t] = (float)hc[t];
    sc[t] = hr[t];
    __syncthreads();
    for (int d = 1; d < NN; d <<= 1) {
        int v = (t >= d) ? sc[t - d] : 0;
        __syncthreads();
        sc[t] += v;
        __syncthreads();
    }
    if (t == 0) g_csr_ptr[b * (NN + 1)] = 0;
    g_csr_ptr[b * (NN + 1) + t + 1] = sc[t];
    off[t] = sc[t] - hr[t];
    __syncthreads();
    for (int e = t; e < EE; e += 256) {
        int r = rows[e];
        int pos = atomicAdd(&off[r], 1);
        g_csr_eid[b * EE + pos] = e;
        g_csr_col[b * EE + pos] = cols[e];
    }
    // edge features: warp per edge, dot(ea[e], wvec) + bmean
    int warp = t >> 5, lane = t & 31;
    float4 w4 = *reinterpret_cast<const float4*>(g_wvec + lane * 4);
    float bm = g_bmean;
    for (int e = warp; e < EE; e += 8) {
        const float* row = ea + ((size_t)b * EE + e) * DD;
        float4 a = *reinterpret_cast<const float4*>(row + lane * 4);
        float d = a.x * w4.x + a.y * w4.y + a.z * w4.z + a.w * w4.w;
        #pragma unroll
        for (int o = 16; o; o >>= 1) d += __shfl_xor_sync(0xFFFFFFFFu, d, o);
        if (lane == 0) g_ef[b * EE + e] = d + bm;
    }
}

// ---------------- kernel 3: QKV via tensor cores (unchanged, measured 49.6us) ------
__global__ void __launch_bounds__(256) k_qkv_mma(const float* __restrict__ x) {
    extern __shared__ __nv_bfloat16 ws[];
    __nv_bfloat16* xh_s = ws;
    __nv_bfloat16* xl_s = ws + 128 * KPS;
    __nv_bfloat16* wh_s = ws + 2 * 128 * KPS;
    __nv_bfloat16* wl_s = wh_s + 16 * WPAD;
    int t = threadIdx.x, warp = t >> 5, lane = t & 31;
    int r0blk = blockIdx.x * 128;
    int r0 = r0blk + warp * 16;

    const float* xb = x + (size_t)r0blk * DD;
    for (int i = t; i < 128 * 32; i += 256) {
        int row = i >> 5, c4 = (i & 31) << 2;
        float4 v = *reinterpret_cast<const float4*>(xb + row * DD + c4);
        __nv_bfloat16 h, l;
        int o = row * KPS + c4;
        bsplit(v.x, h, l); xh_s[o]     = h; xl_s[o]     = l;
        bsplit(v.y, h, l); xh_s[o + 1] = h; xl_s[o + 1] = l;
        bsplit(v.z, h, l); xh_s[o + 2] = h; xl_s[o + 2] = l;
        bsplit(v.w, h, l); xh_s[o + 3] = h; xl_s[o + 3] = l;
    }
    for (int i = t; i < 128 * (KPS - DD); i += 256) {
        int row = i / (KPS - DD), c = DD + i - row * (KPS - DD);
        float v = (c == 128) ? g_deg_r[r0blk + row]
                : (c == 129) ? g_deg_c[r0blk + row] : 0.f;
        __nv_bfloat16 h, l;
        bsplit(v, h, l);
        xh_s[row * KPS + c] = h;
        xl_s[row * KPS + c] = l;
    }

    unsigned xa_off = ((warp * 16 + (lane & 15)) * KPS) * 2 + ((lane >> 4) * 16);
    unsigned xh_base = smem_u32(xh_s) + xa_off;
    unsigned xl_base = smem_u32(xl_s) + xa_off;
    unsigned wb_off = (lane & 15) * (WPAD * 2) + ((lane >> 4) * 16);
    unsigned wh_base = smem_u32(wh_s) + wb_off;
    unsigned wl_base = smem_u32(wl_s) + wb_off;

    int g = lane >> 2;
    int cpair = (lane & 3) * 2;

    for (int m = 0; m < 3; m++) {
        float acc[16][4];
        #pragma unroll
        for (int i = 0; i < 16; i++)
            #pragma unroll
            for (int j = 0; j < 4; j++) acc[i][j] = 0.f;

        for (int kb = 0; kb < KP / 16; kb++) {
            __syncthreads();
            {
                const unsigned* srcH = reinterpret_cast<const unsigned*>(
                    g_wh + (m * KP + kb * 16) * DD);
                const unsigned* srcL = reinterpret_cast<const unsigned*>(
                    g_wl + (m * KP + kb * 16) * DD);
                unsigned* dstH = reinterpret_cast<unsigned*>(wh_s);
                unsigned* dstL = reinterpret_cast<unsigned*>(wl_s);
                #pragma unroll
                for (int i = t; i < 16 * 64; i += 256) {
                    int k = i >> 6, c = i & 63;
                    dstH[k * (WPAD / 2) + c] = srcH[i];
                    dstL[k * (WPAD / 2) + c] = srcL[i];
                }
            }
            __syncthreads();

            unsigned ah0, ah1, ah2, ah3, al0, al1, al2, al3;
            ldsm4(ah0, ah1, ah2, ah3, xh_base + kb * 32);
            ldsm4(al0, al1, al2, al3, xl_base + kb * 32);

            #pragma unroll
            for (int ntp = 0; ntp < 8; ntp++) {
                unsigned bh0, bh1, bh2, bh3, bl0, bl1, bl2, bl3;
                ldsm4t(bh0, bh1, bh2, bh3, wh_base + ntp * 32);
                ldsm4t(bl0, bl1, bl2, bl3, wl_base + ntp * 32);
                mma_bf16(acc[2 * ntp],     ah0, ah1, ah2, ah3, bh0, bh1);
                mma_bf16(acc[2 * ntp],     al0, al1, al2, al3, bh0, bh1);
                mma_bf16(acc[2 * ntp],     ah0, ah1, ah2, ah3, bl0, bl1);
                mma_bf16(acc[2 * ntp + 1], ah0, ah1, ah2, ah3, bh2, bh3);
                mma_bf16(acc[2 * ntp + 1], al0, al1, al2, al3, bh2, bh3);
                mma_bf16(acc[2 * ntp + 1], ah0, ah1, ah2, ah3, bl2, bl3);
            }
        }

        float* out = (m == 0) ? g_q : (m == 1) ? g_k : g_v;
        int tok0 = r0 + g, tok1 = tok0 + 8;
        int b0i = tok0 >> 8, n0i = tok0 & 255;
        int b1i = tok1 >> 8, n1i = tok1 & 255;
        #pragma unroll
        for (int nt = 0; nt < 16; nt++) {
            int c = nt * 8 + cpair;
            int h = c >> 4, dk = c & 15;
            *reinterpret_cast<float2*>(out + ((size_t)(b0i * HH + h) * NN + n0i) * DKK + dk)
                = make_float2(acc[nt][0], acc[nt][1]);
            *reinterpret_cast<float2*>(out + ((size_t)(b1i * HH + h) * NN + n1i) * DKK + dk)
                = make_float2(acc[nt][2], acc[nt][3]);
        }
    }
}

// ---------------- kernel 4: tensor-core attention, register-resident softmax --------
// Block per (b,h), 256 threads. Main loop syncless, no S smem round-trip.
// Sparse edge bias applied afterward per-query in a SIMT pass (exp(s+f)=exp(s)+exp(s)expm1(f)).
__global__ void __launch_bounds__(256) k_attn2() {
    extern __shared__ char asm_[];
    __nv_bfloat16* khT   = reinterpret_cast<__nv_bfloat16*>(asm_);      // [16][KTP]
    __nv_bfloat16* klT   = khT + 16 * KTP;
    __nv_bfloat16* vh_s  = klT + 16 * KTP;                               // [256][16]
    __nv_bfloat16* vl_s  = vh_s + NN * 16;
    __nv_bfloat16* qh_s  = vl_s + NN * 16;                               // [256][16]
    __nv_bfloat16* ql_s  = qh_s + NN * 16;
    float*         krow  = reinterpret_cast<float*>(ql_s + NN * 16);     // [256][16] fp32
    float*         obuf  = krow + NN * 16;                               // [256][16] fp32
    float*         lbuf  = obuf + NN * 16;                               // [256]
    float*         maskb = lbuf + NN;                                    // [256]

    int bh = blockIdx.x, b = bh >> 3, h = bh & 7;
    int t = threadIdx.x, warp = t >> 5, lane = t & 31;
    int g = lane >> 2, cp = (lane & 3) * 2;

    // ---- stage: thread t <-> token t ----
    {
        const float4* qg = reinterpret_cast<const float4*>(g_q + ((size_t)bh * NN + t) * DKK);
        const float4* kg = reinterpret_cast<const float4*>(g_k + ((size_t)bh * NN + t) * DKK);
        const float4* vg = reinterpret_cast<const float4*>(g_v + ((size_t)bh * NN + t) * DKK);
        float qv[16], kv[16], vv[16];
        #pragma unroll
        for (int i = 0; i < 4; i++) {
            float4 a = qg[i];
            qv[4*i] = a.x; qv[4*i+1] = a.y; qv[4*i+2] = a.z; qv[4*i+3] = a.w;
            a = kg[i];
            kv[4*i] = a.x; kv[4*i+1] = a.y; kv[4*i+2] = a.z; kv[4*i+3] = a.w;
            *reinterpret_cast<float4*>(krow + t * 16 + 4 * i) = a;
            a = vg[i];
            vv[4*i] = a.x; vv[4*i+1] = a.y; vv[4*i+2] = a.z; vv[4*i+3] = a.w;
        }
        unsigned* qh = reinterpret_cast<unsigned*>(qh_s) + t * 8;
        unsigned* ql = reinterpret_cast<unsigned*>(ql_s) + t * 8;
        unsigned* vh = reinterpret_cast<unsigned*>(vh_s) + t * 8;
        unsigned* vl = reinterpret_cast<unsigned*>(vl_s) + t * 8;
        #pragma unroll
        for (int i = 0; i < 8; i++) {
            qh[i] = pack_bf2(qv[2*i], qv[2*i+1]);
            ql[i] = pack_bf2_lo(qv[2*i], qv[2*i+1]);
            vh[i] = pack_bf2(vv[2*i], vv[2*i+1]);
            vl[i] = pack_bf2_lo(vv[2*i], vv[2*i+1]);
        }
        #pragma unroll
        for (int dk = 0; dk < 16; dk++) {
            __nv_bfloat16 hh, ll;
            bsplit(kv[dk], hh, ll);
            khT[dk * KTP + t] = hh;
            klT[dk * KTP + t] = ll;
        }
        maskb[t] = g_mask[b * NN + t] ? 0.f : -10000.f;
    }
    __syncthreads();

    // ---- Q A-fragments (persist) ----
    unsigned qfh[2][4], qfl[2][4];
    #pragma unroll
    for (int mi = 0; mi < 2; mi++) {
        unsigned off = ((warp * 32 + mi * 16 + (lane & 15)) * 16) * 2 + (lane >> 4) * 16;
        ldsm4(qfh[mi][0], qfh[mi][1], qfh[mi][2], qfh[mi][3], smem_u32(qh_s) + off);
        ldsm4(qfl[mi][0], qfl[mi][1], qfl[mi][2], qfl[mi][3], smem_u32(ql_s) + off);
    }

    float lsum[2][2] = {{0.f, 0.f}, {0.f, 0.f}};
    float oacc[2][2][4];
    #pragma unroll
    for (int mi = 0; mi < 2; mi++)
        #pragma unroll
        for (int nv = 0; nv < 2; nv++)
            #pragma unroll
            for (int j = 0; j < 4; j++) oacc[mi][nv][j] = 0.f;

    for (int ch = 0; ch < 8; ch++) {
        int c0 = ch * 32;
        // K B-fragments
        unsigned kbh[4][2], kbl[4][2];
        #pragma unroll
        for (int hf = 0; hf < 2; hf++) {
            unsigned off = ((lane & 15) * KTP + c0 + hf * 16) * 2 + (lane >> 4) * 16;
            unsigned r0, r1, r2, r3;
            ldsm4t(r0, r1, r2, r3, smem_u32(khT) + off);
            kbh[2*hf][0] = r0; kbh[2*hf][1] = r1; kbh[2*hf+1][0] = r2; kbh[2*hf+1][1] = r3;
            ldsm4t(r0, r1, r2, r3, smem_u32(klT) + off);
            kbl[2*hf][0] = r0; kbl[2*hf][1] = r1; kbl[2*hf+1][0] = r2; kbl[2*hf+1][1] = r3;
        }
        // V B-fragments (hoisted: shared across mi)
        unsigned vfh[2][4], vfl[2][4];
        #pragma unroll
        for (int kt = 0; kt < 2; kt++) {
            unsigned voff = ((c0 + kt * 16 + (lane & 15)) * 16) * 2 + (lane >> 4) * 16;
            ldsm4t(vfh[kt][0], vfh[kt][1], vfh[kt][2], vfh[kt][3], smem_u32(vh_s) + voff);
            ldsm4t(vfl[kt][0], vfl[kt][1], vfl[kt][2], vfl[kt][3], smem_u32(vl_s) + voff);
        }
        // mask biases for this chunk's columns (same for both mi, both sub-rows)
        float2 mb[4];
        #pragma unroll
        for (int nt = 0; nt < 4; nt++)
            mb[nt] = *reinterpret_cast<float2*>(&maskb[c0 + nt * 8 + cp]);

        #pragma unroll
        for (int mi = 0; mi < 2; mi++) {
            // QK^T (split x3), keep in registers
            float pe[4][4];
            float rs0 = 0.f, rs1 = 0.f;
            #pragma unroll
            for (int nt = 0; nt < 4; nt++) {
                float S[4] = {0.f, 0.f, 0.f, 0.f};
                mma_bf16(S, qfh[mi][0], qfh[mi][1], qfh[mi][2], qfh[mi][3], kbh[nt][0], kbh[nt][1]);
                mma_bf16(S, qfl[mi][0], qfl[mi][1], qfl[mi][2], qfl[mi][3], kbh[nt][0], kbh[nt][1]);
                mma_bf16(S, qfh[mi][0], qfh[mi][1], qfh[mi][2], qfh[mi][3], kbl[nt][0], kbl[nt][1]);
                pe[nt][0] = __expf(S[0] * 0.25f + mb[nt].x);
                pe[nt][1] = __expf(S[1] * 0.25f + mb[nt].y);
                pe[nt][2] = __expf(S[2] * 0.25f + mb[nt].x);
                pe[nt][3] = __expf(S[3] * 0.25f + mb[nt].y);
                rs0 += pe[nt][0] + pe[nt][1];
                rs1 += pe[nt][2] + pe[nt][3];
            }
            rs0 += __shfl_xor_sync(0xFFFFFFFFu, rs0, 1);
            rs0 += __shfl_xor_sync(0xFFFFFFFFu, rs0, 2);
            rs1 += __shfl_xor_sync(0xFFFFFFFFu, rs1, 1);
            rs1 += __shfl_xor_sync(0xFFFFFFFFu, rs1, 2);
            lsum[mi][0] += rs0;
            lsum[mi][1] += rs1;
            // P c-frag -> A-frag repack (register-only) + PV
            #pragma unroll
            for (int kt = 0; kt < 2; kt++) {
                unsigned pah0 = pack_bf2(pe[2*kt][0],   pe[2*kt][1]);
                unsigned pah1 = pack_bf2(pe[2*kt][2],   pe[2*kt][3]);
                unsigned pah2 = pack_bf2(pe[2*kt+1][0], pe[2*kt+1][1]);
                unsigned pah3 = pack_bf2(pe[2*kt+1][2], pe[2*kt+1][3]);
                unsigned pal0 = pack_bf2_lo(pe[2*kt][0],   pe[2*kt][1]);
                unsigned pal1 = pack_bf2_lo(pe[2*kt][2],   pe[2*kt][3]);
                unsigned pal2 = pack_bf2_lo(pe[2*kt+1][0], pe[2*kt+1][1]);
                unsigned pal3 = pack_bf2_lo(pe[2*kt+1][2], pe[2*kt+1][3]);
                mma_bf16(oacc[mi][0], pah0, pah1, pah2, pah3, vfh[kt][0], vfh[kt][1]);
                mma_bf16(oacc[mi][0], pal0, pal1, pal2, pal3, vfh[kt][0], vfh[kt][1]);
                mma_bf16(oacc[mi][0], pah0, pah1, pah2, pah3, vfl[kt][0], vfl[kt][1]);
                mma_bf16(oacc[mi][1], pah0, pah1, pah2, pah3, vfh[kt][2], vfh[kt][3]);
                mma_bf16(oacc[mi][1], pal0, pal1, pal2, pal3, vfh[kt][2], vfh[kt][3]);
                mma_bf16(oacc[mi][1], pah0, pah1, pah2, pah3, vfl[kt][2], vfl[kt][3]);
            }
        }
    }

    // ---- dump unnormalized O and rowsums to smem ----
    #pragma unroll
    for (int mi = 0; mi < 2; mi++) {
        int r0 = warp * 32 + mi * 16 + g;
        #pragma unroll
        for (int nv = 0; nv < 2; nv++) {
            int dk = nv * 8 + cp;
            *reinterpret_cast<float2*>(&obuf[r0 * 16 + dk])
                = make_float2(oacc[mi][nv][0], oacc[mi][nv][1]);
            *reinterpret_cast<float2*>(&obuf[(r0 + 8) * 16 + dk])
                = make_float2(oacc[mi][nv][2], oacc[mi][nv][3]);
        }
        if ((lane & 3) == 0) {
            lbuf[r0] = lsum[mi][0];
            lbuf[r0 + 8] = lsum[mi][1];
        }
    }
    __syncthreads();

    // ---- sparse edge-bias correction + normalize: thread t = query t ----
    {
        float o[16];
        #pragma unroll
        for (int i = 0; i < 4; i++) {
            float4 v = *reinterpret_cast<float4*>(&obuf[t * 16 + 4 * i]);
            o[4*i] = v.x; o[4*i+1] = v.y; o[4*i+2] = v.z; o[4*i+3] = v.w;
        }
        float l = lbuf[t];
        int p0 = g_csr_ptr[b * (NN + 1) + t];
        int p1 = g_csr_ptr[b * (NN + 1) + t + 1];
        if (p1 > p0) {
            float q[16];
            const float4* qg = reinterpret_cast<const float4*>(
                g_q + ((size_t)bh * NN + t) * DKK);
            #pragma unroll
            for (int i = 0; i < 4; i++) {
                float4 v = qg[i];
                q[4*i] = v.x; q[4*i+1] = v.y; q[4*i+2] = v.z; q[4*i+3] = v.w;
            }
            int base = b * EE;
            for (int idx = p0; idx < p1; idx++) {
                int c = g_csr_col[base + idx];
                float f = g_ef[base + g_csr_eid[base + idx]];
                const float* kc = krow + c * 16;
                float s = 0.f;
                #pragma unroll
                for (int d = 0; d < 16; d++) s += q[d] * kc[d];
                float w = __expf(s * 0.25f + maskb[c]) * expm1f(f);
                l += w;
                const __nv_bfloat16* vh = vh_s + c * 16;
                const __nv_bfloat16* vl = vl_s + c * 16;
                #pragma unroll
                for (int d = 0; d < 16; d++)
                    o[d] += w * (__bfloat162float(vh[d]) + __bfloat162float(vl[d]));
            }
        }
        float inv = 1.0f / l;
        float* og = g_o + ((size_t)(b * NN + t)) * DD + h * 16;
        #pragma unroll
        for (int i = 0; i < 4; i++)
            reinterpret_cast<float4*>(og)[i] = make_float4(
                o[4*i] * inv, o[4*i+1] * inv, o[4*i+2] * inv, o[4*i+3] * inv);
    }
}

// ---------------- kernel 5: residual + layernorm ----------------
__global__ void k_ln(const float* __restrict__ x,
                     const float* __restrict__ lg,
                     const float* __restrict__ lb,
                     float* __restrict__ out) {
    int warp = threadIdx.x >> 5, lane = threadIdx.x & 31;
    int row = blockIdx.x * 8 + warp;
    int c0 = lane * 4;
    float4 o = *reinterpret_cast<const float4*>(g_o + (size_t)row * DD + c0);
    float4 xv = *reinterpret_cast<const float4*>(x + (size_t)row * DD + c0);
    float4 s = make_float4(o.x + xv.x, o.y + xv.y, o.z + xv.z, o.w + xv.w);
    float sum = s.x + s.y + s.z + s.w;
    float sq  = s.x * s.x + s.y * s.y + s.z * s.z + s.w * s.w;
    #pragma unroll
    for (int off = 16; off; off >>= 1) {
        sum += __shfl_xor_sync(0xFFFFFFFFu, sum, off);
        sq  += __shfl_xor_sync(0xFFFFFFFFu, sq, off);
    }
    float mu = sum * (1.0f / DD);
    float var = sq * (1.0f / DD) - mu * mu;
    float rstd = rsqrtf(var + 1e-6f);
    float4 g = *reinterpret_cast<const float4*>(lg + c0);
    float4 be = *reinterpret_cast<const float4*>(lb + c0);
    float4 r;
    r.x = (s.x - mu) * rstd * g.x + be.x;
    r.y = (s.y - mu) * rstd * g.y + be.y;
    r.z = (s.z - mu) * rstd * g.z + be.z;
    r.w = (s.w - mu) * rstd * g.w + be.w;
    *reinterpret_cast<float4*>(out + (size_t)row * DD + c0) = r;
}

// ---------------- launch ----------------
extern "C" void kernel_launch(void* const* d_in, const int* in_sizes, int n_in,
                              void* d_out, int out_size) {
    const float* x    = (const float*)d_in[0];
    const void*  mask = d_in[1];
    const int*   ei   = (const int*)d_in[2];
    const float* ea   = (const float*)d_in[3];
    const float* Wq   = (const float*)d_in[4];
    const float* Wk   = (const float*)d_in[5];
    const float* Wv   = (const float*)d_in[6];
    const float* Wew  = (const float*)d_in[7];
    const float* Web  = (const float*)d_in[8];
    const float* lg   = (const float*)d_in[9];
    const float* lb   = (const float*)d_in[10];
    float* out = (float*)d_out;

    k_mask_conv<<<128 + (3 * KP * DD) / 256, 256>>>(mask, Wew, Web, Wq, Wk, Wv);
    k_deg_csr<<<BB, 256>>>(ei, ea);

    int smem_mma = (2 * 128 * KPS + 2 * 16 * WPAD) * (int)sizeof(__nv_bfloat16);
    cudaFuncSetAttribute(k_qkv_mma, cudaFuncAttributeMaxDynamicSharedMemorySize, smem_mma);
    k_qkv_mma<<<(BB * NN) / 128, 256, smem_mma>>>(x);

    // launch #4 — profiled slot
    int smem_attn = (2 * 16 * KTP + 4 * NN * 16) * (int)sizeof(__nv_bfloat16)
                  + (2 * NN * 16 + 2 * NN) * (int)sizeof(float) + 16;
    cudaFuncSetAttribute(k_attn2, cudaFuncAttributeMaxDynamicSharedMemorySize, smem_attn);
    k_attn2<<<BB * HH, 256, smem_attn>>>();

    k_ln<<<(BB * NN) / 8, 256>>>(x, lg, lb, out);
}

// round 17
// speedup vs baseline: 1.6526x; 1.4107x over previous
#include <cuda_runtime.h>
#include <cuda_bf16.h>
#include <math.h>

#define BB 128
#define NN 256
#define EE 1024
#define DD 128
#define HH 8
#define DKK 16
#define DIN 130   // D + 2 degree features
#define KP  144   // K padded to 9 * 16
#define KPS 152   // x smem row stride (bf16)
#define WPAD 136  // W smem row stride (bf16)
#define KTP 264   // K^T smem row stride (bf16)

// ---------------- scratch (device globals; no runtime allocation) ----------------
__device__ float g_deg_r[BB * NN];
__device__ float g_deg_c[BB * NN];
__device__ float g_q[BB * HH * NN * DKK];
__device__ float g_k[BB * HH * NN * DKK];
__device__ float g_v[BB * HH * NN * DKK];
__device__ float g_ef[BB * EE];
__device__ float g_wvec[DD];
__device__ float g_bmean;
__device__ float g_o[BB * NN * DD];
__device__ int   g_mask[BB * NN];
__device__ int   g_csr_ptr[BB * (NN + 1)];
__device__ int   g_csr_eid[BB * EE];
__device__ int   g_csr_col[BB * EE];
__device__ int   g_klist[BB * NN];
__device__ int   g_kinv[BB * NN];
__device__ int   g_kcnt[BB];
__device__ __nv_bfloat16 g_wh[3 * KP * DD];
__device__ __nv_bfloat16 g_wl[3 * KP * DD];

// ---------------- helpers ----------------
__device__ __forceinline__ unsigned smem_u32(const void* p) {
    return (unsigned)__cvta_generic_to_shared(p);
}
__device__ __forceinline__ void ldsm4(unsigned& r0, unsigned& r1, unsigned& r2,
                                      unsigned& r3, unsigned addr) {
    asm volatile("ldmatrix.sync.aligned.m8n8.x4.shared.b16 {%0,%1,%2,%3}, [%4];"
                 : "=r"(r0), "=r"(r1), "=r"(r2), "=r"(r3) : "r"(addr));
}
__device__ __forceinline__ void ldsm4t(unsigned& r0, unsigned& r1, unsigned& r2,
                                       unsigned& r3, unsigned addr) {
    asm volatile("ldmatrix.sync.aligned.m8n8.x4.trans.shared.b16 {%0,%1,%2,%3}, [%4];"
                 : "=r"(r0), "=r"(r1), "=r"(r2), "=r"(r3) : "r"(addr));
}
__device__ __forceinline__ void mma_bf16(float* c, unsigned a0, unsigned a1,
                                         unsigned a2, unsigned a3,
                                         unsigned b0, unsigned b1) {
    asm volatile("mma.sync.aligned.m16n8k16.row.col.f32.bf16.bf16.f32 "
                 "{%0,%1,%2,%3}, {%4,%5,%6,%7}, {%8,%9}, {%0,%1,%2,%3};"
                 : "+f"(c[0]), "+f"(c[1]), "+f"(c[2]), "+f"(c[3])
                 : "r"(a0), "r"(a1), "r"(a2), "r"(a3), "r"(b0), "r"(b1));
}
__device__ __forceinline__ void bsplit(float v, __nv_bfloat16& h, __nv_bfloat16& l) {
    h = __float2bfloat16(v);
    l = __float2bfloat16(v - __bfloat162float(h));
}
__device__ __forceinline__ unsigned pack_bf2(float x, float y) {
    __nv_bfloat162 v = __floats2bfloat162_rn(x, y);
    return *reinterpret_cast<unsigned*>(&v);
}
__device__ __forceinline__ unsigned pack_bf2_lo(float x, float y) {
    __nv_bfloat16 hx = __float2bfloat16(x), hy = __float2bfloat16(y);
    float lx = x - __bfloat162float(hx), ly = y - __bfloat162float(hy);
    __nv_bfloat162 v = __floats2bfloat162_rn(lx, ly);
    return *reinterpret_cast<unsigned*>(&v);
}

// ---------------- kernel 1: mask normalize + wvec (blocks<128) | W split (>=128) ----
__global__ void k_mask_conv(const void* __restrict__ mp,
                            const float* __restrict__ Wew,
                            const float* __restrict__ Web,
                            const float* __restrict__ Wq,
                            const float* __restrict__ Wk,
                            const float* __restrict__ Wv) {
    if (blockIdx.x >= 128) {
        int j = (blockIdx.x - 128) * 256 + threadIdx.x;
        int m = j / (KP * DD);
        int rem = j - m * (KP * DD);
        int k = rem / DD, n = rem - k * DD;
        const float* W = (m == 0) ? Wq : (m == 1) ? Wk : Wv;
        float v = (k < DIN) ? W[k * DD + n] : 0.f;
        __nv_bfloat16 h, l;
        bsplit(v, h, l);
        g_wh[j] = h;
        g_wl[j] = l;
        return;
    }
    const unsigned int* mw = reinterpret_cast<const unsigned int*>(mp);
    __shared__ int c_f32, c_big;
    if (threadIdx.x == 0) { c_f32 = 0; c_big = 0; }
    __syncthreads();
    int nf = 0, nb = 0;
    for (int i = threadIdx.x; i < 8192; i += 256) {
        unsigned int w = mw[i];
        if (w == 0x3F800000u) nf++;
        else if (w > 1u) nb++;
    }
    if (nf) atomicAdd(&c_f32, nf);
    if (nb) atomicAdd(&c_big, nb);
    __syncthreads();
    int f = (c_f32 > 64) ? 2 : (c_big > 64) ? 0 : 1;
    int i = blockIdx.x * 256 + threadIdx.x;
    int v;
    if (f == 2)      v = (reinterpret_cast<const float*>(mp)[i] != 0.0f);
    else if (f == 1) v = (reinterpret_cast<const int*>(mp)[i] != 0);
    else             v = (reinterpret_cast<const unsigned char*>(mp)[i] != 0);
    g_mask[i] = v;

    if (blockIdx.x == 0 && threadIdx.x < DD) {
        int r = threadIdx.x;
        float s = 0.f;
        for (int j = 0; j < DD; j++) s += Wew[r * DD + j];
        g_wvec[r] = s * (1.0f / DD);
        if (r == 0) {
            float b = 0.f;
            for (int j = 0; j < DD; j++) b += Web[j];
            g_bmean = b * (1.0f / DD);
        }
    }
}

// ---------------- kernel 2: degrees + row-CSR + compacted key list + inverse map ----
__global__ void k_deg_csr(const int* __restrict__ ei) {
    int b = blockIdx.x, t = threadIdx.x;  // 256 threads
    __shared__ int hr[NN], hc[NN], sc[NN], off[NN];
    hr[t] = 0; hc[t] = 0;
    __syncthreads();
    const int* rows = ei + b * 2 * EE;
    const int* cols = rows + EE;
    for (int e = t; e < EE; e += 256) {
        atomicAdd(&hr[rows[e]], 1);
        atomicAdd(&hc[cols[e]], 1);
    }
    __syncthreads();
    g_deg_r[b * NN + t] = (float)hr[t];
    g_deg_c[b * NN + t] = (float)hc[t];
    sc[t] = hr[t];
    __syncthreads();
    for (int d = 1; d < NN; d <<= 1) {
        int v = (t >= d) ? sc[t - d] : 0;
        __syncthreads();
        sc[t] += v;
        __syncthreads();
    }
    if (t == 0) g_csr_ptr[b * (NN + 1)] = 0;
    g_csr_ptr[b * (NN + 1) + t + 1] = sc[t];
    off[t] = sc[t] - hr[t];
    __syncthreads();
    for (int e = t; e < EE; e += 256) {
        int r = rows[e];
        int pos = atomicAdd(&off[r], 1);
        g_csr_eid[b * EE + pos] = e;
        g_csr_col[b * EE + pos] = cols[e];
    }
    // compacted active-key list + inverse map
    __syncthreads();
    int mv = g_mask[b * NN + t];
    sc[t] = mv;
    __syncthreads();
    for (int d = 1; d < NN; d <<= 1) {
        int v = (t >= d) ? sc[t - d] : 0;
        __syncthreads();
        sc[t] += v;
        __syncthreads();
    }
    if (mv) {
        g_klist[b * NN + sc[t] - 1] = t;
        g_kinv[b * NN + t] = sc[t] - 1;
    } else {
        g_kinv[b * NN + t] = -1;
    }
    if (t == NN - 1) g_kcnt[b] = sc[t];
}

// ---------------- kernel 3: QKV via tensor cores | blocks>=256 do edge features ----
__global__ void __launch_bounds__(256) k_qkv_mma(const float* __restrict__ x,
                                                 const float* __restrict__ ea) {
    int t = threadIdx.x;
    if (blockIdx.x >= 256) {
        // edge features: 2048 blocks x 8 warps x 8 edges
        int warp = t >> 5, lane = t & 31;
        float4 w4 = *reinterpret_cast<const float4*>(g_wvec + lane * 4);
        float bm = g_bmean;
        int e0 = (((int)blockIdx.x - 256) * 8 + warp) * 8;
        for (int e = e0; e < e0 + 8; e++) {
            const float* row = ea + (size_t)e * DD;
            float4 a = *reinterpret_cast<const float4*>(row + lane * 4);
            float d = a.x * w4.x + a.y * w4.y + a.z * w4.z + a.w * w4.w;
            #pragma unroll
            for (int o = 16; o; o >>= 1) d += __shfl_xor_sync(0xFFFFFFFFu, d, o);
            if (lane == 0) g_ef[e] = d + bm;
        }
        return;
    }
    extern __shared__ __nv_bfloat16 ws[];
    __nv_bfloat16* xh_s = ws;
    __nv_bfloat16* xl_s = ws + 128 * KPS;
    __nv_bfloat16* wh_s = ws + 2 * 128 * KPS;
    __nv_bfloat16* wl_s = wh_s + 16 * WPAD;
    int warp = t >> 5, lane = t & 31;
    int r0blk = blockIdx.x * 128;
    int r0 = r0blk + warp * 16;

    const float* xb = x + (size_t)r0blk * DD;
    for (int i = t; i < 128 * 32; i += 256) {
        int row = i >> 5, c4 = (i & 31) << 2;
        float4 v = *reinterpret_cast<const float4*>(xb + row * DD + c4);
        __nv_bfloat16 h, l;
        int o = row * KPS + c4;
        bsplit(v.x, h, l); xh_s[o]     = h; xl_s[o]     = l;
        bsplit(v.y, h, l); xh_s[o + 1] = h; xl_s[o + 1] = l;
        bsplit(v.z, h, l); xh_s[o + 2] = h; xl_s[o + 2] = l;
        bsplit(v.w, h, l); xh_s[o + 3] = h; xl_s[o + 3] = l;
    }
    for (int i = t; i < 128 * (KPS - DD); i += 256) {
        int row = i / (KPS - DD), c = DD + i - row * (KPS - DD);
        float v = (c == 128) ? g_deg_r[r0blk + row]
                : (c == 129) ? g_deg_c[r0blk + row] : 0.f;
        __nv_bfloat16 h, l;
        bsplit(v, h, l);
        xh_s[row * KPS + c] = h;
        xl_s[row * KPS + c] = l;
    }

    unsigned xa_off = ((warp * 16 + (lane & 15)) * KPS) * 2 + ((lane >> 4) * 16);
    unsigned xh_base = smem_u32(xh_s) + xa_off;
    unsigned xl_base = smem_u32(xl_s) + xa_off;
    unsigned wb_off = (lane & 15) * (WPAD * 2) + ((lane >> 4) * 16);
    unsigned wh_base = smem_u32(wh_s) + wb_off;
    unsigned wl_base = smem_u32(wl_s) + wb_off;

    int g = lane >> 2;
    int cpair = (lane & 3) * 2;

    for (int m = 0; m < 3; m++) {
        float acc[16][4];
        #pragma unroll
        for (int i = 0; i < 16; i++)
            #pragma unroll
            for (int j = 0; j < 4; j++) acc[i][j] = 0.f;

        for (int kb = 0; kb < KP / 16; kb++) {
            __syncthreads();
            {
                const unsigned* srcH = reinterpret_cast<const unsigned*>(
                    g_wh + (m * KP + kb * 16) * DD);
                const unsigned* srcL = reinterpret_cast<const unsigned*>(
                    g_wl + (m * KP + kb * 16) * DD);
                unsigned* dstH = reinterpret_cast<unsigned*>(wh_s);
                unsigned* dstL = reinterpret_cast<unsigned*>(wl_s);
                #pragma unroll
                for (int i = t; i < 16 * 64; i += 256) {
                    int k = i >> 6, c = i & 63;
                    dstH[k * (WPAD / 2) + c] = srcH[i];
                    dstL[k * (WPAD / 2) + c] = srcL[i];
                }
            }
            __syncthreads();

            unsigned ah0, ah1, ah2, ah3, al0, al1, al2, al3;
            ldsm4(ah0, ah1, ah2, ah3, xh_base + kb * 32);
            ldsm4(al0, al1, al2, al3, xl_base + kb * 32);

            #pragma unroll
            for (int ntp = 0; ntp < 8; ntp++) {
                unsigned bh0, bh1, bh2, bh3, bl0, bl1, bl2, bl3;
                ldsm4t(bh0, bh1, bh2, bh3, wh_base + ntp * 32);
                ldsm4t(bl0, bl1, bl2, bl3, wl_base + ntp * 32);
                mma_bf16(acc[2 * ntp],     ah0, ah1, ah2, ah3, bh0, bh1);
                mma_bf16(acc[2 * ntp],     al0, al1, al2, al3, bh0, bh1);
                mma_bf16(acc[2 * ntp],     ah0, ah1, ah2, ah3, bl0, bl1);
                mma_bf16(acc[2 * ntp + 1], ah0, ah1, ah2, ah3, bh2, bh3);
                mma_bf16(acc[2 * ntp + 1], al0, al1, al2, al3, bh2, bh3);
                mma_bf16(acc[2 * ntp + 1], ah0, ah1, ah2, ah3, bl2, bl3);
            }
        }

        float* out = (m == 0) ? g_q : (m == 1) ? g_k : g_v;
        int tok0 = r0 + g, tok1 = tok0 + 8;
        int b0i = tok0 >> 8, n0i = tok0 & 255;
        int b1i = tok1 >> 8, n1i = tok1 & 255;
        #pragma unroll
        for (int nt = 0; nt < 16; nt++) {
            int c = nt * 8 + cpair;
            int h = c >> 4, dk = c & 15;
            *reinterpret_cast<float2*>(out + ((size_t)(b0i * HH + h) * NN + n0i) * DKK + dk)
                = make_float2(acc[nt][0], acc[nt][1]);
            *reinterpret_cast<float2*>(out + ((size_t)(b1i * HH + h) * NN + n1i) * DKK + dk)
                = make_float2(acc[nt][2], acc[nt][3]);
        }
    }
}

// ---------------- kernel 4: tensor-core attention with key compaction --------------
// Block per (b,h), 256 threads. K/V staged compacted (active keys only);
// main loop runs ceil(cnt/32) chunks. Sparse bias corrected in SIMT pass after.
__global__ void __launch_bounds__(256) k_attn2() {
    extern __shared__ char asm_[];
    __nv_bfloat16* khT   = reinterpret_cast<__nv_bfloat16*>(asm_);      // [16][KTP]
    __nv_bfloat16* klT   = khT + 16 * KTP;
    __nv_bfloat16* vh_s  = klT + 16 * KTP;                               // [256][16]
    __nv_bfloat16* vl_s  = vh_s + NN * 16;
    __nv_bfloat16* qh_s  = vl_s + NN * 16;                               // [256][16]
    __nv_bfloat16* ql_s  = qh_s + NN * 16;
    float*         krow  = reinterpret_cast<float*>(ql_s + NN * 16);     // [256][16] fp32
    float*         obuf  = krow + NN * 16;                               // [256][16] fp32
    float*         lbuf  = obuf + NN * 16;                               // [256]
    float*         maskb = lbuf + NN;                                    // [256]

    int bh = blockIdx.x, b = bh >> 3, h = bh & 7;
    int t = threadIdx.x, warp = t >> 5, lane = t & 31;
    int g = lane >> 2, cp = (lane & 3) * 2;
    int cnt = g_kcnt[b];

    // ---- stage: Q for token t; K/V for compacted slot t ----
    {
        const float4* qg = reinterpret_cast<const float4*>(g_q + ((size_t)bh * NN + t) * DKK);
        float qv[16], kv[16], vv[16];
        #pragma unroll
        for (int i = 0; i < 4; i++) {
            float4 a = qg[i];
            qv[4*i] = a.x; qv[4*i+1] = a.y; qv[4*i+2] = a.z; qv[4*i+3] = a.w;
        }
        if (t < cnt) {
            int kt = g_klist[b * NN + t];
            const float4* kg = reinterpret_cast<const float4*>(g_k + ((size_t)bh * NN + kt) * DKK);
            const float4* vg = reinterpret_cast<const float4*>(g_v + ((size_t)bh * NN + kt) * DKK);
            #pragma unroll
            for (int i = 0; i < 4; i++) {
                float4 a = kg[i];
                kv[4*i] = a.x; kv[4*i+1] = a.y; kv[4*i+2] = a.z; kv[4*i+3] = a.w;
                *reinterpret_cast<float4*>(krow + t * 16 + 4 * i) = a;
                a = vg[i];
                vv[4*i] = a.x; vv[4*i+1] = a.y; vv[4*i+2] = a.z; vv[4*i+3] = a.w;
            }
        } else {
            #pragma unroll
            for (int i = 0; i < 16; i++) { kv[i] = 0.f; vv[i] = 0.f; }
        }
        unsigned* qh = reinterpret_cast<unsigned*>(qh_s) + t * 8;
        unsigned* ql = reinterpret_cast<unsigned*>(ql_s) + t * 8;
        unsigned* vh = reinterpret_cast<unsigned*>(vh_s) + t * 8;
        unsigned* vl = reinterpret_cast<unsigned*>(vl_s) + t * 8;
        #pragma unroll
        for (int i = 0; i < 8; i++) {
            qh[i] = pack_bf2(qv[2*i], qv[2*i+1]);
            ql[i] = pack_bf2_lo(qv[2*i], qv[2*i+1]);
            vh[i] = pack_bf2(vv[2*i], vv[2*i+1]);
            vl[i] = pack_bf2_lo(vv[2*i], vv[2*i+1]);
        }
        #pragma unroll
        for (int dk = 0; dk < 16; dk++) {
            __nv_bfloat16 hh, ll;
            bsplit(kv[dk], hh, ll);
            khT[dk * KTP + t] = hh;
            klT[dk * KTP + t] = ll;
        }
        maskb[t] = (t < cnt) ? 0.f : -10000.f;
    }
    __syncthreads();

    // ---- Q A-fragments (persist) ----
    unsigned qfh[2][4], qfl[2][4];
    #pragma unroll
    for (int mi = 0; mi < 2; mi++) {
        unsigned off = ((warp * 32 + mi * 16 + (lane & 15)) * 16) * 2 + (lane >> 4) * 16;
        ldsm4(qfh[mi][0], qfh[mi][1], qfh[mi][2], qfh[mi][3], smem_u32(qh_s) + off);
        ldsm4(qfl[mi][0], qfl[mi][1], qfl[mi][2], qfl[mi][3], smem_u32(ql_s) + off);
    }

    float lsum[2][2] = {{0.f, 0.f}, {0.f, 0.f}};
    float oacc[2][2][4];
    #pragma unroll
    for (int mi = 0; mi < 2; mi++)
        #pragma unroll
        for (int nv = 0; nv < 2; nv++)
            #pragma unroll
            for (int j = 0; j < 4; j++) oacc[mi][nv][j] = 0.f;

    int nch = (cnt + 31) >> 5;
    for (int ch = 0; ch < nch; ch++) {
        int c0 = ch * 32;
        unsigned kbh[4][2], kbl[4][2];
        #pragma unroll
        for (int hf = 0; hf < 2; hf++) {
            unsigned off = ((lane & 15) * KTP + c0 + hf * 16) * 2 + (lane >> 4) * 16;
            unsigned r0, r1, r2, r3;
            ldsm4t(r0, r1, r2, r3, smem_u32(khT) + off);
            kbh[2*hf][0] = r0; kbh[2*hf][1] = r1; kbh[2*hf+1][0] = r2; kbh[2*hf+1][1] = r3;
            ldsm4t(r0, r1, r2, r3, smem_u32(klT) + off);
            kbl[2*hf][0] = r0; kbl[2*hf][1] = r1; kbl[2*hf+1][0] = r2; kbl[2*hf+1][1] = r3;
        }
        unsigned vfh[2][4], vfl[2][4];
        #pragma unroll
        for (int kt = 0; kt < 2; kt++) {
            unsigned voff = ((c0 + kt * 16 + (lane & 15)) * 16) * 2 + (lane >> 4) * 16;
            ldsm4t(vfh[kt][0], vfh[kt][1], vfh[kt][2], vfh[kt][3], smem_u32(vh_s) + voff);
            ldsm4t(vfl[kt][0], vfl[kt][1], vfl[kt][2], vfl[kt][3], smem_u32(vl_s) + voff);
        }
        float2 mb[4];
        #pragma unroll
        for (int nt = 0; nt < 4; nt++)
            mb[nt] = *reinterpret_cast<float2*>(&maskb[c0 + nt * 8 + cp]);

        #pragma unroll
        for (int mi = 0; mi < 2; mi++) {
            float pe[4][4];
            float rs0 = 0.f, rs1 = 0.f;
            #pragma unroll
            for (int nt = 0; nt < 4; nt++) {
                float S[4] = {0.f, 0.f, 0.f, 0.f};
                mma_bf16(S, qfh[mi][0], qfh[mi][1], qfh[mi][2], qfh[mi][3], kbh[nt][0], kbh[nt][1]);
                mma_bf16(S, qfl[mi][0], qfl[mi][1], qfl[mi][2], qfl[mi][3], kbh[nt][0], kbh[nt][1]);
                mma_bf16(S, qfh[mi][0], qfh[mi][1], qfh[mi][2], qfh[mi][3], kbl[nt][0], kbl[nt][1]);
                pe[nt][0] = __expf(S[0] * 0.25f + mb[nt].x);
                pe[nt][1] = __expf(S[1] * 0.25f + mb[nt].y);
                pe[nt][2] = __expf(S[2] * 0.25f + mb[nt].x);
                pe[nt][3] = __expf(S[3] * 0.25f + mb[nt].y);
                rs0 += pe[nt][0] + pe[nt][1];
                rs1 += pe[nt][2] + pe[nt][3];
            }
            rs0 += __shfl_xor_sync(0xFFFFFFFFu, rs0, 1);
            rs0 += __shfl_xor_sync(0xFFFFFFFFu, rs0, 2);
            rs1 += __shfl_xor_sync(0xFFFFFFFFu, rs1, 1);
            rs1 += __shfl_xor_sync(0xFFFFFFFFu, rs1, 2);
            lsum[mi][0] += rs0;
            lsum[mi][1] += rs1;
            #pragma unroll
            for (int kt = 0; kt < 2; kt++) {
                unsigned pah0 = pack_bf2(pe[2*kt][0],   pe[2*kt][1]);
                unsigned pah1 = pack_bf2(pe[2*kt][2],   pe[2*kt][3]);
                unsigned pah2 = pack_bf2(pe[2*kt+1][0], pe[2*kt+1][1]);
                unsigned pah3 = pack_bf2(pe[2*kt+1][2], pe[2*kt+1][3]);
                unsigned pal0 = pack_bf2_lo(pe[2*kt][0],   pe[2*kt][1]);
                unsigned pal1 = pack_bf2_lo(pe[2*kt][2],   pe[2*kt][3]);
                unsigned pal2 = pack_bf2_lo(pe[2*kt+1][0], pe[2*kt+1][1]);
                unsigned pal3 = pack_bf2_lo(pe[2*kt+1][2], pe[2*kt+1][3]);
                mma_bf16(oacc[mi][0], pah0, pah1, pah2, pah3, vfh[kt][0], vfh[kt][1]);
                mma_bf16(oacc[mi][0], pal0, pal1, pal2, pal3, vfh[kt][0], vfh[kt][1]);
                mma_bf16(oacc[mi][0], pah0, pah1, pah2, pah3, vfl[kt][0], vfl[kt][1]);
                mma_bf16(oacc[mi][1], pah0, pah1, pah2, pah3, vfh[kt][2], vfh[kt][3]);
                mma_bf16(oacc[mi][1], pal0, pal1, pal2, pal3, vfh[kt][2], vfh[kt][3]);
                mma_bf16(oacc[mi][1], pah0, pah1, pah2, pah3, vfl[kt][2], vfl[kt][3]);
            }
        }
    }

    // ---- dump unnormalized O and rowsums to smem ----
    #pragma unroll
    for (int mi = 0; mi < 2; mi++) {
        int r0 = warp * 32 + mi * 16 + g;
        #pragma unroll
        for (int nv = 0; nv < 2; nv++) {
            int dk = nv * 8 + cp;
            *reinterpret_cast<float2*>(&obuf[r0 * 16 + dk])
                = make_float2(oacc[mi][nv][0], oacc[mi][nv][1]);
            *reinterpret_cast<float2*>(&obuf[(r0 + 8) * 16 + dk])
                = make_float2(oacc[mi][nv][2], oacc[mi][nv][3]);
        }
        if ((lane & 3) == 0) {
            lbuf[r0] = lsum[mi][0];
            lbuf[r0 + 8] = lsum[mi][1];
        }
    }
    __syncthreads();

    // ---- sparse edge-bias correction + normalize: thread t = query t ----
    {
        float o[16];
        #pragma unroll
        for (int i = 0; i < 4; i++) {
            float4 v = *reinterpret_cast<float4*>(&obuf[t * 16 + 4 * i]);
            o[4*i] = v.x; o[4*i+1] = v.y; o[4*i+2] = v.z; o[4*i+3] = v.w;
        }
        float l = lbuf[t];
        int p0 = g_csr_ptr[b * (NN + 1) + t];
        int p1 = g_csr_ptr[b * (NN + 1) + t + 1];
        if (p1 > p0) {
            float q[16];
            const float4* qg = reinterpret_cast<const float4*>(
                g_q + ((size_t)bh * NN + t) * DKK);
            #pragma unroll
            for (int i = 0; i < 4; i++) {
                float4 v = qg[i];
                q[4*i] = v.x; q[4*i+1] = v.y; q[4*i+2] = v.z; q[4*i+3] = v.w;
            }
            int base = b * EE;
            for (int idx = p0; idx < p1; idx++) {
                int c = g_csr_col[base + idx];
                int slot = g_kinv[b * NN + c];
                if (slot < 0) continue;   // masked key -> contribution exactly 0
                float f = g_ef[base + g_csr_eid[base + idx]];
                const float* kc = krow + slot * 16;
                float s = 0.f;
                #pragma unroll
                for (int d = 0; d < 16; d++) s += q[d] * kc[d];
                float w = __expf(s * 0.25f) * expm1f(f);
                l += w;
                const __nv_bfloat16* vh = vh_s + slot * 16;
                const __nv_bfloat16* vl = vl_s + slot * 16;
                #pragma unroll
                for (int d = 0; d < 16; d++)
                    o[d] += w * (__bfloat162float(vh[d]) + __bfloat162float(vl[d]));
            }
        }
        float inv = 1.0f / l;
        float* og = g_o + ((size_t)(b * NN + t)) * DD + h * 16;
        #pragma unroll
        for (int i = 0; i < 4; i++)
            reinterpret_cast<float4*>(og)[i] = make_float4(
                o[4*i] * inv, o[4*i+1] * inv, o[4*i+2] * inv, o[4*i+3] * inv);
    }
}

// ---------------- kernel 5: residual + layernorm ----------------
__global__ void k_ln(const float* __restrict__ x,
                     const float* __restrict__ lg,
                     const float* __restrict__ lb,
                     float* __restrict__ out) {
    int warp = threadIdx.x >> 5, lane = threadIdx.x & 31;
    int row = blockIdx.x * 8 + warp;
    int c0 = lane * 4;
    float4 o = *reinterpret_cast<const float4*>(g_o + (size_t)row * DD + c0);
    float4 xv = *reinterpret_cast<const float4*>(x + (size_t)row * DD + c0);
    float4 s = make_float4(o.x + xv.x, o.y + xv.y, o.z + xv.z, o.w + xv.w);
    float sum = s.x + s.y + s.z + s.w;
    float sq  = s.x * s.x + s.y * s.y + s.z * s.z + s.w * s.w;
    #pragma unroll
    for (int off = 16; off; off >>= 1) {
        sum += __shfl_xor_sync(0xFFFFFFFFu, sum, off);
        sq  += __shfl_xor_sync(0xFFFFFFFFu, sq, off);
    }
    float mu = sum * (1.0f / DD);
    float var = sq * (1.0f / DD) - mu * mu;
    float rstd = rsqrtf(var + 1e-6f);
    float4 g = *reinterpret_cast<const float4*>(lg + c0);
    float4 be = *reinterpret_cast<const float4*>(lb + c0);
    float4 r;
    r.x = (s.x - mu) * rstd * g.x + be.x;
    r.y = (s.y - mu) * rstd * g.y + be.y;
    r.z = (s.z - mu) * rstd * g.z + be.z;
    r.w = (s.w - mu) * rstd * g.w + be.w;
    *reinterpret_cast<float4*>(out + (size_t)row * DD + c0) = r;
}

// ---------------- launch ----------------
extern "C" void kernel_launch(void* const* d_in, const int* in_sizes, int n_in,
                              void* d_out, int out_size) {
    const float* x    = (const float*)d_in[0];
    const void*  mask = d_in[1];
    const int*   ei   = (const int*)d_in[2];
    const float* ea   = (const float*)d_in[3];
    const float* Wq   = (const float*)d_in[4];
    const float* Wk   = (const float*)d_in[5];
    const float* Wv   = (const float*)d_in[6];
    const float* Wew  = (const float*)d_in[7];
    const float* Web  = (const float*)d_in[8];
    const float* lg   = (const float*)d_in[9];
    const float* lb   = (const float*)d_in[10];
    float* out = (float*)d_out;

    k_mask_conv<<<128 + (3 * KP * DD) / 256, 256>>>(mask, Wew, Web, Wq, Wk, Wv);
    k_deg_csr<<<BB, 256>>>(ei);

    int smem_mma = (2 * 128 * KPS + 2 * 16 * WPAD) * (int)sizeof(__nv_bfloat16);
    cudaFuncSetAttribute(k_qkv_mma, cudaFuncAttributeMaxDynamicSharedMemorySize, smem_mma);
    k_qkv_mma<<<256 + 2048, 256, smem_mma>>>(x, ea);   // blocks >= 256 do edge features

    // launch #4 — profiled slot
    int smem_attn = (2 * 16 * KTP + 4 * NN * 16) * (int)sizeof(__nv_bfloat16)
                  + (2 * NN * 16 + 2 * NN) * (int)sizeof(float) + 16;
    cudaFuncSetAttribute(k_attn2, cudaFuncAttributeMaxDynamicSharedMemorySize, smem_attn);
    k_attn2<<<BB * HH, 256, smem_attn>>>();

    k_ln<<<(BB * NN) / 8, 256>>>(x, lg, lb, out);
}